// round 7
// baseline (speedup 1.0000x reference)
#include <cuda_runtime.h>
#include <cstdint>

// ---------------------------------------------------------------------------
// QuantumNeuralNetwork: fused MLP + 4-qubit expval + classifier
//
// Math reduction: variational circuit has batch-shared weights, so
//   <Z0> = e^T Re(U' Z0 U) e  with U the fixed 16x16 circuit unitary and
//   e the real RY-embedding product state. M = Re(U' Z0 U) is precomputed
//   once per launch by build_M_kernel.
//
// R6: bank-conflict-free weight layout for the image GEMM. iW1 is stored as
// two 32-column half-arrays; the second half's base is skewed +16B (mod 128)
// so the 8 float4 b-loads of a quarter-warp phase cover all 32 banks exactly
// once. b-load wavefronts per k-step drop 2x.
// ---------------------------------------------------------------------------

#define XS 128   // smem row stride for transposed input tiles (a-loads broadcast)

// smem float offsets
#define OFF_WI1A   0                       // [48][32] cols 0-31
#define OFF_WI1B   (48*32 + 4)             // [48][32] cols 32-63, +16B skew
#define OFF_XTI    (OFF_WI1B + 48*32 + 4)  // [48][XS]
#define OFF_XTT    (OFF_XTI + 48*XS)       // [16][XS]
#define OFF_WT1    (OFF_XTT + 16*XS)       // [16][32]
#define OFF_WI2T   (OFF_WT1 + 512)         // [4][64]
#define OFF_WT2T   (OFF_WI2T + 256)        // [4][32]
#define OFF_IB1    (OFF_WT2T + 128)        // [64]
#define OFF_TB1    (OFF_IB1 + 64)          // [32]
#define OFF_B2     (OFF_TB1 + 32)          // [4]
#define OFF_MS     (OFF_B2 + 4)            // [16][16]
#define OFF_CLS    (OFF_MS + 256)          // cW1[16] cb1[16] cW2[32] cb2[2]
#define SMEM_FLOATS (OFF_CLS + 68)

__device__ __align__(16) float g_M[256];

// ---------------------------------------------------------------------------
// Prologue: build M[16][16] = Re(U^dagger Z0 U) from qweights [2][4][3].
// ---------------------------------------------------------------------------
__global__ void build_M_kernel(const float* __restrict__ qw) {
    __shared__ float Ure[16][16], Uim[16][16];
    const int k = threadIdx.x;  // column index 0..15
    float vr[16], vi[16];
#pragma unroll
    for (int n = 0; n < 16; n++) { vr[n] = (n == k) ? 1.f : 0.f; vi[n] = 0.f; }

    for (int l = 0; l < 2; l++) {
        for (int i = 0; i < 4; i++) {
            float phi = qw[(l*4 + i)*3 + 0];
            float th  = qw[(l*4 + i)*3 + 1];
            float om  = qw[(l*4 + i)*3 + 2];
            float ct = cosf(0.5f*th), st = sinf(0.5f*th);
            float sp, cp, sm, cm;
            sincosf(0.5f*(phi + om), &sp, &cp);
            sincosf(0.5f*(phi - om), &sm, &cm);
            float u00r =  cp*ct, u00i = -sp*ct;
            float u01r = -cm*st, u01i = -sm*st;
            float u10r =  cm*st, u10i = -sm*st;
            float u11r =  cp*ct, u11i =  sp*ct;
            int mask = 1 << (3 - i);
#pragma unroll
            for (int n = 0; n < 16; n++) {
                if (n & mask) continue;
                int n1 = n | mask;
                float r0 = vr[n],  i0 = vi[n];
                float r1 = vr[n1], i1 = vi[n1];
                vr[n]  = u00r*r0 - u00i*i0 + u01r*r1 - u01i*i1;
                vi[n]  = u00r*i0 + u00i*r0 + u01r*i1 + u01i*r1;
                vr[n1] = u10r*r0 - u10i*i0 + u11r*r1 - u11i*i1;
                vi[n1] = u10r*i0 + u10i*r0 + u11r*i1 + u11i*r1;
            }
        }
        for (int i = 0; i < 3; i++) {
            int m1 = 1 << (3 - i), m2 = 1 << (2 - i);
#pragma unroll
            for (int n = 0; n < 16; n++)
                if ((n & m1) && (n & m2)) { vr[n] = -vr[n]; vi[n] = -vi[n]; }
        }
    }
#pragma unroll
    for (int n = 0; n < 16; n++) { Ure[n][k] = vr[n]; Uim[n][k] = vi[n]; }
    __syncthreads();
#pragma unroll
    for (int j = 0; j < 16; j++) {
        float acc = 0.f;
#pragma unroll
        for (int b = 0; b < 16; b++) {
            float z = (b & 8) ? -1.f : 1.f;
            acc += z * (Ure[b][j]*Ure[b][k] + Uim[b][j]*Uim[b][k]);
        }
        g_M[j*16 + k] = acc;
    }
}

// ---------------------------------------------------------------------------
// Main fused kernel: 128 threads handle 128 samples per block.
// ---------------------------------------------------------------------------
__global__ __launch_bounds__(128) void qnn_kernel(
    const float* __restrict__ text, const float* __restrict__ image,
    const float* __restrict__ tW1,  const float* __restrict__ tb1,
    const float* __restrict__ tW2,  const float* __restrict__ tb2,
    const float* __restrict__ iW1,  const float* __restrict__ ib1,
    const float* __restrict__ iW2,  const float* __restrict__ ib2,
    const float* __restrict__ cW1,  const float* __restrict__ cb1,
    const float* __restrict__ cW2,  const float* __restrict__ cb2,
    float* __restrict__ out)
{
    extern __shared__ __align__(128) float smf[];
    float* wI1a = smf + OFF_WI1A;
    float* wI1b = smf + OFF_WI1B;
    float* xTi  = smf + OFF_XTI;
    float* xTt  = smf + OFF_XTT;
    float* wT1s = smf + OFF_WT1;
    float* wI2t = smf + OFF_WI2T;
    float* wT2t = smf + OFF_WT2T;
    float* ib1s = smf + OFF_IB1;
    float* tb1s = smf + OFF_TB1;
    float* b2s  = smf + OFF_B2;
    float* Ms   = smf + OFF_MS;
    float* cls  = smf + OFF_CLS;
    float* feats = xTi;                // aliased after GEMMs: [128][4]

    const int tid = threadIdx.x;
    const size_t base = (size_t)blockIdx.x * 128;

    // ---- stage inputs + weights into shared ----
    {
        const float4* ig = (const float4*)(image + base * 48);
#pragma unroll
        for (int it = 0; it < 12; it++) {
            int idx = it*128 + tid;
            float4 v = ig[idx];
            int s = idx / 12;
            int kq = idx - s*12;
            float* p = &xTi[(4*kq)*XS + s];
            p[0] = v.x; p[XS] = v.y; p[2*XS] = v.z; p[3*XS] = v.w;
        }
        const float4* tg = (const float4*)(text + base * 16);
#pragma unroll
        for (int it = 0; it < 4; it++) {
            int idx = it*128 + tid;
            float4 v = tg[idx];
            int s = idx >> 2;
            int kq = idx & 3;
            float* p = &xTt[(4*kq)*XS + s];
            p[0] = v.x; p[XS] = v.y; p[2*XS] = v.z; p[3*XS] = v.w;
        }
        // iW1 [48][64] -> split halves with 16B-skewed second half
#pragma unroll
        for (int it = 0; it < 6; it++) {
            int idx = it*128 + tid;            // float4 index 0..767
            float4 v = ((const float4*)iW1)[idx];
            int kk = idx >> 4;                 // row 0..47
            int nb = idx & 15;                 // block-of-4 within row
            float* dst = (nb < 8) ? &wI1a[kk*32 + nb*4]
                                  : &wI1b[kk*32 + (nb-8)*4];
            *(float4*)dst = v;
        }
        ((float4*)wT1s)[tid] = ((const float4*)tW1)[tid];
        if (tid < 64) {
            float4 w = ((const float4*)iW2)[tid];   // row tid of iW2[64][4]
            wI2t[tid] = w.x; wI2t[64+tid] = w.y; wI2t[128+tid] = w.z; wI2t[192+tid] = w.w;
            ib1s[tid] = ib1[tid];
            ((float4*)Ms)[tid] = ((const float4*)g_M)[tid];
        }
        if (tid < 32) {
            float4 w = ((const float4*)tW2)[tid];   // row tid of tW2[32][4]
            wT2t[tid] = w.x; wT2t[32+tid] = w.y; wT2t[64+tid] = w.z; wT2t[96+tid] = w.w;
            tb1s[tid] = tb1[tid];
        }
        if (tid < 16) {
            cls[tid] = cW1[tid]; cls[16+tid] = cb1[tid];
            cls[32+2*tid] = cW2[2*tid]; cls[33+2*tid] = cW2[2*tid+1];
        }
        if (tid < 4) b2s[tid] = ib2[tid] + tb2[tid];
        if (tid < 2) cls[64+tid] = cb2[tid];
    }
    __syncthreads();

    const int trow = tid >> 3;        // 0..15 : sample group
    const int tcol = tid & 7;         // 0..7  : neuron / k-chunk group
    const int m0 = trow * 8;

    // ---- image MLP1: 128x64, K=48, microtile 8x8 ----
    const int n0 = tcol * 8;
    // conflict-free weight base: tcol 0-3 -> first half, 4-7 -> skewed half
    const float* wb = (tcol < 4) ? (wI1a + n0) : (wI1b + (n0 - 32));

    float acc[8][8];
#pragma unroll
    for (int i = 0; i < 8; i++)
#pragma unroll
        for (int j = 0; j < 8; j++) acc[i][j] = 0.f;

#pragma unroll 8
    for (int k = 0; k < 48; k++) {
        float4 a0 = *(const float4*)&xTi[k*XS + m0];
        float4 a1 = *(const float4*)&xTi[k*XS + m0 + 4];
        float4 b0 = *(const float4*)&wb[k*32];
        float4 b1 = *(const float4*)&wb[k*32 + 4];
        float a[8] = {a0.x,a0.y,a0.z,a0.w,a1.x,a1.y,a1.z,a1.w};
        float b[8] = {b0.x,b0.y,b0.z,b0.w,b1.x,b1.y,b1.z,b1.w};
#pragma unroll
        for (int i = 0; i < 8; i++)
#pragma unroll
            for (int j = 0; j < 8; j++)
                acc[i][j] = fmaf(a[i], b[j], acc[i][j]);
    }

    // ---- fold into imf partials: relu(h2)·iW2 over this thread's 8 neurons ----
    float pv[8][4];
#pragma unroll
    for (int i = 0; i < 8; i++)
#pragma unroll
        for (int n = 0; n < 4; n++) pv[i][n] = 0.f;

#pragma unroll
    for (int j = 0; j < 8; j++) {
        int nj = n0 + j;
        float w0 = wI2t[nj], w1 = wI2t[64+nj], w2 = wI2t[128+nj], w3 = wI2t[192+nj];
        float bj = ib1s[nj];
#pragma unroll
        for (int i = 0; i < 8; i++) {
            float h = fmaxf(acc[i][j] + bj, 0.f);
            pv[i][0] = fmaf(h, w0, pv[i][0]);
            pv[i][1] = fmaf(h, w1, pv[i][1]);
            pv[i][2] = fmaf(h, w2, pv[i][2]);
            pv[i][3] = fmaf(h, w3, pv[i][3]);
        }
    }

    // ---- text MLP1: 128x32, K=16, microtile 8x4 (rows are 128B: conflict-free)
    const int t0 = tcol * 4;
    float acc2[8][4];
#pragma unroll
    for (int i = 0; i < 8; i++)
#pragma unroll
        for (int j = 0; j < 4; j++) acc2[i][j] = 0.f;

#pragma unroll
    for (int k = 0; k < 16; k++) {
        float4 a0 = *(const float4*)&xTt[k*XS + m0];
        float4 a1 = *(const float4*)&xTt[k*XS + m0 + 4];
        float4 b  = *(const float4*)&wT1s[k*32 + t0];
        float a[8] = {a0.x,a0.y,a0.z,a0.w,a1.x,a1.y,a1.z,a1.w};
#pragma unroll
        for (int i = 0; i < 8; i++) {
            acc2[i][0] = fmaf(a[i], b.x, acc2[i][0]);
            acc2[i][1] = fmaf(a[i], b.y, acc2[i][1]);
            acc2[i][2] = fmaf(a[i], b.z, acc2[i][2]);
            acc2[i][3] = fmaf(a[i], b.w, acc2[i][3]);
        }
    }
#pragma unroll
    for (int j = 0; j < 4; j++) {
        int nj = t0 + j;
        float w0 = wT2t[nj], w1 = wT2t[32+nj], w2 = wT2t[64+nj], w3 = wT2t[96+nj];
        float bj = tb1s[nj];
#pragma unroll
        for (int i = 0; i < 8; i++) {
            float h = fmaxf(acc2[i][j] + bj, 0.f);
            pv[i][0] = fmaf(h, w0, pv[i][0]);
            pv[i][1] = fmaf(h, w1, pv[i][1]);
            pv[i][2] = fmaf(h, w2, pv[i][2]);
            pv[i][3] = fmaf(h, w3, pv[i][3]);
        }
    }

    // ---- reduce partials across the 8 k-chunk lanes (consecutive lanes) ----
#pragma unroll
    for (int i = 0; i < 8; i++)
#pragma unroll
        for (int n = 0; n < 4; n++) {
            float v = pv[i][n];
            v += __shfl_xor_sync(0xffffffffu, v, 4);
            v += __shfl_xor_sync(0xffffffffu, v, 2);
            v += __shfl_xor_sync(0xffffffffu, v, 1);
            pv[i][n] = v;
        }

    __syncthreads();   // everyone done reading xTi/xTt before feats alias write
    if (tcol == 0) {
        float4 bb = *(const float4*)b2s;
#pragma unroll
        for (int i = 0; i < 8; i++) {
            float4 fo;
            fo.x = 0.5f * (pv[i][0] + bb.x);
            fo.y = 0.5f * (pv[i][1] + bb.y);
            fo.z = 0.5f * (pv[i][2] + bb.z);
            fo.w = 0.5f * (pv[i][3] + bb.w);
            *(float4*)&feats[(m0 + i) * 4] = fo;
        }
    }
    __syncthreads();

    // ---- quantum expval + classifier: one sample per thread ----
    float4 f = *(const float4*)&feats[tid * 4];
    float c0, q0s, c1, q1s, c2, q2s, c3, q3s;
    __sincosf(0.5f*f.x, &q0s, &c0);
    __sincosf(0.5f*f.y, &q1s, &c1);
    __sincosf(0.5f*f.z, &q2s, &c2);
    __sincosf(0.5f*f.w, &q3s, &c3);

    float p01[4] = {c0*c1, c0*q1s, q0s*c1, q0s*q1s};
    float p23[4] = {c2*c3, c2*q3s, q2s*c3, q2s*q3s};
    float e[16];
#pragma unroll
    for (int a = 0; a < 4; a++)
#pragma unroll
        for (int b = 0; b < 4; b++) e[a*4+b] = p01[a] * p23[b];

    float q = 0.f;
#pragma unroll
    for (int j = 0; j < 16; j++) {
        const float4* Mr = (const float4*)&Ms[j*16];
        float4 r0 = Mr[0], r1 = Mr[1], r2 = Mr[2], r3 = Mr[3];
        float tj = r0.x*e[0] + r0.y*e[1] + r0.z*e[2] + r0.w*e[3]
                 + r1.x*e[4] + r1.y*e[5] + r1.z*e[6] + r1.w*e[7]
                 + r2.x*e[8] + r2.y*e[9] + r2.z*e[10] + r2.w*e[11]
                 + r3.x*e[12] + r3.y*e[13] + r3.z*e[14] + r3.w*e[15];
        q = fmaf(e[j], tj, q);
    }

    float o0 = cls[64], o1 = cls[65];
#pragma unroll
    for (int m = 0; m < 16; m++) {
        float h = fmaxf(fmaf(q, cls[m], cls[16+m]), 0.f);
        o0 = fmaf(h, cls[32+2*m], o0);
        o1 = fmaf(h, cls[33+2*m], o1);
    }
    float2 res; res.x = o0; res.y = o1;
    ((float2*)out)[base + tid] = res;
}

// ---------------------------------------------------------------------------
extern "C" void kernel_launch(void* const* d_in, const int* in_sizes, int n_in,
                              void* d_out, int out_size) {
    const float* text = (const float*)d_in[0];
    const float* image= (const float*)d_in[1];
    const float* tW1  = (const float*)d_in[2];
    const float* tb1  = (const float*)d_in[3];
    const float* tW2  = (const float*)d_in[4];
    const float* tb2  = (const float*)d_in[5];
    const float* iW1  = (const float*)d_in[6];
    const float* ib1  = (const float*)d_in[7];
    const float* iW2  = (const float*)d_in[8];
    const float* ib2  = (const float*)d_in[9];
    const float* qw   = (const float*)d_in[10];
    const float* cW1  = (const float*)d_in[11];
    const float* cb1  = (const float*)d_in[12];
    const float* cW2  = (const float*)d_in[13];
    const float* cb2  = (const float*)d_in[14];
    float* out = (float*)d_out;

    const int B = in_sizes[0] / 16;
    const int grid = B / 128;
    const size_t smem = SMEM_FLOATS * sizeof(float);

    cudaFuncSetAttribute(qnn_kernel, cudaFuncAttributeMaxDynamicSharedMemorySize, (int)smem);

    build_M_kernel<<<1, 16>>>(qw);
    qnn_kernel<<<grid, 128, smem>>>(text, image, tW1, tb1, tW2, tb2,
                                    iW1, ib1, iW2, ib2,
                                    cW1, cb1, cW2, cb2, out);
}

// round 9
// speedup vs baseline: 1.1488x; 1.1488x over previous
#include <cuda_runtime.h>
#include <cstdint>

// ---------------------------------------------------------------------------
// QuantumNeuralNetwork: fused MLP + 4-qubit expval + classifier
//
// <Z0> = e^T M e with M = Re(U' Z0 U) precomputed by build_M_kernel.
//
// R7: kill the staging transpose. Inputs stored ROW-major in smem with odd
// padded stride (49 / 17 floats): staging is coalesced LDG + near-conflict-
// free STS.32; GEMM a-operand read as 8x LDS.32 (stride 49 -> banks
// {0,8,16,24}+c per instruction, broadcast across tcol lanes = 1 wf each).
// Weight arrays keep the R6 conflict-free split+skew layout.
// ---------------------------------------------------------------------------

#define XRS 49   // image tile row stride (floats), odd -> conflict-free LDS.32
#define XTS 17   // text  tile row stride

#define OFF_WI1A   0                        // [48][32] cols 0-31
#define OFF_WI1B   (48*32 + 4)              // [48][32] cols 32-63, +16B skew
#define OFF_XRI    (OFF_WI1B + 48*32 + 4)   // [128][XRS] image tile row-major
#define OFF_XRT    (OFF_XRI + 128*XRS)      // [128][XTS] text tile row-major
#define OFF_WT1    (OFF_XRT + 128*XTS)      // [16][32]
#define OFF_WI2T   (OFF_WT1 + 512)          // [4][64]
#define OFF_WT2T   (OFF_WI2T + 256)         // [4][32]
#define OFF_IB1    (OFF_WT2T + 128)         // [64]
#define OFF_TB1    (OFF_IB1 + 64)           // [32]
#define OFF_B2     (OFF_TB1 + 32)           // [4]
#define OFF_MS     (OFF_B2 + 4)             // [16][16]
#define OFF_CLS    (OFF_MS + 256)           // cW1[16] cb1[16] cW2[32] cb2[2]
#define SMEM_FLOATS (OFF_CLS + 68)

__device__ __align__(16) float g_M[256];

// ---------------------------------------------------------------------------
// Prologue: build M[16][16] = Re(U^dagger Z0 U) from qweights [2][4][3].
// ---------------------------------------------------------------------------
__global__ void build_M_kernel(const float* __restrict__ qw) {
    __shared__ float Ure[16][16], Uim[16][16];
    const int k = threadIdx.x;  // column index 0..15
    float vr[16], vi[16];
#pragma unroll
    for (int n = 0; n < 16; n++) { vr[n] = (n == k) ? 1.f : 0.f; vi[n] = 0.f; }

    for (int l = 0; l < 2; l++) {
        for (int i = 0; i < 4; i++) {
            float phi = qw[(l*4 + i)*3 + 0];
            float th  = qw[(l*4 + i)*3 + 1];
            float om  = qw[(l*4 + i)*3 + 2];
            float ct = cosf(0.5f*th), st = sinf(0.5f*th);
            float sp, cp, sm, cm;
            sincosf(0.5f*(phi + om), &sp, &cp);
            sincosf(0.5f*(phi - om), &sm, &cm);
            float u00r =  cp*ct, u00i = -sp*ct;
            float u01r = -cm*st, u01i = -sm*st;
            float u10r =  cm*st, u10i = -sm*st;
            float u11r =  cp*ct, u11i =  sp*ct;
            int mask = 1 << (3 - i);
#pragma unroll
            for (int n = 0; n < 16; n++) {
                if (n & mask) continue;
                int n1 = n | mask;
                float r0 = vr[n],  i0 = vi[n];
                float r1 = vr[n1], i1 = vi[n1];
                vr[n]  = u00r*r0 - u00i*i0 + u01r*r1 - u01i*i1;
                vi[n]  = u00r*i0 + u00i*r0 + u01r*i1 + u01i*r1;
                vr[n1] = u10r*r0 - u10i*i0 + u11r*r1 - u11i*i1;
                vi[n1] = u10r*i0 + u10i*r0 + u11r*i1 + u11i*r1;
            }
        }
        for (int i = 0; i < 3; i++) {
            int m1 = 1 << (3 - i), m2 = 1 << (2 - i);
#pragma unroll
            for (int n = 0; n < 16; n++)
                if ((n & m1) && (n & m2)) { vr[n] = -vr[n]; vi[n] = -vi[n]; }
        }
    }
#pragma unroll
    for (int n = 0; n < 16; n++) { Ure[n][k] = vr[n]; Uim[n][k] = vi[n]; }
    __syncthreads();
#pragma unroll
    for (int j = 0; j < 16; j++) {
        float acc = 0.f;
#pragma unroll
        for (int b = 0; b < 16; b++) {
            float z = (b & 8) ? -1.f : 1.f;
            acc += z * (Ure[b][j]*Ure[b][k] + Uim[b][j]*Uim[b][k]);
        }
        g_M[j*16 + k] = acc;
    }
}

// ---------------------------------------------------------------------------
// Main fused kernel: 128 threads handle 128 samples per block.
// ---------------------------------------------------------------------------
__global__ __launch_bounds__(128) void qnn_kernel(
    const float* __restrict__ text, const float* __restrict__ image,
    const float* __restrict__ tW1,  const float* __restrict__ tb1,
    const float* __restrict__ tW2,  const float* __restrict__ tb2,
    const float* __restrict__ iW1,  const float* __restrict__ ib1,
    const float* __restrict__ iW2,  const float* __restrict__ ib2,
    const float* __restrict__ cW1,  const float* __restrict__ cb1,
    const float* __restrict__ cW2,  const float* __restrict__ cb2,
    float* __restrict__ out)
{
    extern __shared__ __align__(128) float smf[];
    float* wI1a = smf + OFF_WI1A;
    float* wI1b = smf + OFF_WI1B;
    float* xRi  = smf + OFF_XRI;
    float* xRt  = smf + OFF_XRT;
    float* wT1s = smf + OFF_WT1;
    float* wI2t = smf + OFF_WI2T;
    float* wT2t = smf + OFF_WT2T;
    float* ib1s = smf + OFF_IB1;
    float* tb1s = smf + OFF_TB1;
    float* b2s  = smf + OFF_B2;
    float* Ms   = smf + OFF_MS;
    float* cls  = smf + OFF_CLS;
    float* feats = xRi;                // aliased after GEMMs: [128][4]

    const int tid = threadIdx.x;
    const size_t base = (size_t)blockIdx.x * 128;

    // ---- stage inputs + weights into shared ----
    {
        // image: coalesced LDG, row-major STS (stride 49 -> ~2-way worst case)
        const float4* ig = (const float4*)(image + base * 48);
#pragma unroll
        for (int it = 0; it < 12; it++) {
            int idx = it*128 + tid;
            float4 v = ig[idx];
            int s  = idx / 12;
            int kq = idx - s*12;
            float* p = &xRi[s*XRS + 4*kq];
            p[0] = v.x; p[1] = v.y; p[2] = v.z; p[3] = v.w;
        }
        // text: same pattern
        const float4* tg = (const float4*)(text + base * 16);
#pragma unroll
        for (int it = 0; it < 4; it++) {
            int idx = it*128 + tid;
            float4 v = tg[idx];
            int s  = idx >> 2;
            int kq = idx & 3;
            float* p = &xRt[s*XTS + 4*kq];
            p[0] = v.x; p[1] = v.y; p[2] = v.z; p[3] = v.w;
        }
        // iW1 [48][64] -> split halves with 16B-skewed second half
#pragma unroll
        for (int it = 0; it < 6; it++) {
            int idx = it*128 + tid;            // float4 index 0..767
            float4 v = ((const float4*)iW1)[idx];
            int kk = idx >> 4;                 // row 0..47
            int nb = idx & 15;                 // block-of-4 within row
            float* dst = (nb < 8) ? &wI1a[kk*32 + nb*4]
                                  : &wI1b[kk*32 + (nb-8)*4];
            *(float4*)dst = v;
        }
        ((float4*)wT1s)[tid] = ((const float4*)tW1)[tid];
        if (tid < 64) {
            float4 w = ((const float4*)iW2)[tid];   // row tid of iW2[64][4]
            wI2t[tid] = w.x; wI2t[64+tid] = w.y; wI2t[128+tid] = w.z; wI2t[192+tid] = w.w;
            ib1s[tid] = ib1[tid];
            ((float4*)Ms)[tid] = ((const float4*)g_M)[tid];
        }
        if (tid < 32) {
            float4 w = ((const float4*)tW2)[tid];   // row tid of tW2[32][4]
            wT2t[tid] = w.x; wT2t[32+tid] = w.y; wT2t[64+tid] = w.z; wT2t[96+tid] = w.w;
            tb1s[tid] = tb1[tid];
        }
        if (tid < 16) {
            cls[tid] = cW1[tid]; cls[16+tid] = cb1[tid];
            cls[32+2*tid] = cW2[2*tid]; cls[33+2*tid] = cW2[2*tid+1];
        }
        if (tid < 4) b2s[tid] = ib2[tid] + tb2[tid];
        if (tid < 2) cls[64+tid] = cb2[tid];
    }
    __syncthreads();

    const int trow = tid >> 3;        // 0..15 : sample group
    const int tcol = tid & 7;         // 0..7  : neuron group
    const int m0 = trow * 8;

    // ---- image MLP1: 128x64, K=48, microtile 8x8 ----
    const int n0 = tcol * 8;
    const float* wb = (tcol < 4) ? (wI1a + n0) : (wI1b + (n0 - 32));
    const float* xb = xRi + m0 * XRS;

    float acc[8][8];
#pragma unroll
    for (int i = 0; i < 8; i++)
#pragma unroll
        for (int j = 0; j < 8; j++) acc[i][j] = 0.f;

#pragma unroll 8
    for (int k = 0; k < 48; k++) {
        float a[8];
#pragma unroll
        for (int i = 0; i < 8; i++) a[i] = xb[i*XRS + k];
        float4 b0 = *(const float4*)&wb[k*32];
        float4 b1 = *(const float4*)&wb[k*32 + 4];
        float b[8] = {b0.x,b0.y,b0.z,b0.w,b1.x,b1.y,b1.z,b1.w};
#pragma unroll
        for (int i = 0; i < 8; i++)
#pragma unroll
            for (int j = 0; j < 8; j++)
                acc[i][j] = fmaf(a[i], b[j], acc[i][j]);
    }

    // ---- fold into imf partials: relu(h2)·iW2 over this thread's 8 neurons ----
    float pv[8][4];
#pragma unroll
    for (int i = 0; i < 8; i++)
#pragma unroll
        for (int n = 0; n < 4; n++) pv[i][n] = 0.f;

#pragma unroll
    for (int j = 0; j < 8; j++) {
        int nj = n0 + j;
        float w0 = wI2t[nj], w1 = wI2t[64+nj], w2 = wI2t[128+nj], w3 = wI2t[192+nj];
        float bj = ib1s[nj];
#pragma unroll
        for (int i = 0; i < 8; i++) {
            float h = fmaxf(acc[i][j] + bj, 0.f);
            pv[i][0] = fmaf(h, w0, pv[i][0]);
            pv[i][1] = fmaf(h, w1, pv[i][1]);
            pv[i][2] = fmaf(h, w2, pv[i][2]);
            pv[i][3] = fmaf(h, w3, pv[i][3]);
        }
    }

    // ---- text MLP1: 128x32, K=16, microtile 8x4 ----
    const int t0 = tcol * 4;
    const float* xt = xRt + m0 * XTS;
    float acc2[8][4];
#pragma unroll
    for (int i = 0; i < 8; i++)
#pragma unroll
        for (int j = 0; j < 4; j++) acc2[i][j] = 0.f;

#pragma unroll
    for (int k = 0; k < 16; k++) {
        float a[8];
#pragma unroll
        for (int i = 0; i < 8; i++) a[i] = xt[i*XTS + k];
        float4 b = *(const float4*)&wT1s[k*32 + t0];
#pragma unroll
        for (int i = 0; i < 8; i++) {
            acc2[i][0] = fmaf(a[i], b.x, acc2[i][0]);
            acc2[i][1] = fmaf(a[i], b.y, acc2[i][1]);
            acc2[i][2] = fmaf(a[i], b.z, acc2[i][2]);
            acc2[i][3] = fmaf(a[i], b.w, acc2[i][3]);
        }
    }
#pragma unroll
    for (int j = 0; j < 4; j++) {
        int nj = t0 + j;
        float w0 = wT2t[nj], w1 = wT2t[32+nj], w2 = wT2t[64+nj], w3 = wT2t[96+nj];
        float bj = tb1s[nj];
#pragma unroll
        for (int i = 0; i < 8; i++) {
            float h = fmaxf(acc2[i][j] + bj, 0.f);
            pv[i][0] = fmaf(h, w0, pv[i][0]);
            pv[i][1] = fmaf(h, w1, pv[i][1]);
            pv[i][2] = fmaf(h, w2, pv[i][2]);
            pv[i][3] = fmaf(h, w3, pv[i][3]);
        }
    }

    // ---- reduce partials across the 8 neuron-group lanes ----
#pragma unroll
    for (int i = 0; i < 8; i++)
#pragma unroll
        for (int n = 0; n < 4; n++) {
            float v = pv[i][n];
            v += __shfl_xor_sync(0xffffffffu, v, 4);
            v += __shfl_xor_sync(0xffffffffu, v, 2);
            v += __shfl_xor_sync(0xffffffffu, v, 1);
            pv[i][n] = v;
        }

    __syncthreads();   // everyone done reading xRi/xRt before feats alias write
    if (tcol == 0) {
        float4 bb = *(const float4*)b2s;
#pragma unroll
        for (int i = 0; i < 8; i++) {
            float4 fo;
            fo.x = 0.5f * (pv[i][0] + bb.x);
            fo.y = 0.5f * (pv[i][1] + bb.y);
            fo.z = 0.5f * (pv[i][2] + bb.z);
            fo.w = 0.5f * (pv[i][3] + bb.w);
            *(float4*)&feats[(m0 + i) * 4] = fo;
        }
    }
    __syncthreads();

    // ---- quantum expval + classifier: one sample per thread ----
    float4 f = *(const float4*)&feats[tid * 4];
    float c0, q0s, c1, q1s, c2, q2s, c3, q3s;
    __sincosf(0.5f*f.x, &q0s, &c0);
    __sincosf(0.5f*f.y, &q1s, &c1);
    __sincosf(0.5f*f.z, &q2s, &c2);
    __sincosf(0.5f*f.w, &q3s, &c3);

    float p01[4] = {c0*c1, c0*q1s, q0s*c1, q0s*q1s};
    float p23[4] = {c2*c3, c2*q3s, q2s*c3, q2s*q3s};
    float e[16];
#pragma unroll
    for (int a = 0; a < 4; a++)
#pragma unroll
        for (int b = 0; b < 4; b++) e[a*4+b] = p01[a] * p23[b];

    float q = 0.f;
#pragma unroll
    for (int j = 0; j < 16; j++) {
        const float4* Mr = (const float4*)&Ms[j*16];
        float4 r0 = Mr[0], r1 = Mr[1], r2 = Mr[2], r3 = Mr[3];
        float tj = r0.x*e[0] + r0.y*e[1] + r0.z*e[2] + r0.w*e[3]
                 + r1.x*e[4] + r1.y*e[5] + r1.z*e[6] + r1.w*e[7]
                 + r2.x*e[8] + r2.y*e[9] + r2.z*e[10] + r2.w*e[11]
                 + r3.x*e[12] + r3.y*e[13] + r3.z*e[14] + r3.w*e[15];
        q = fmaf(e[j], tj, q);
    }

    float o0 = cls[64], o1 = cls[65];
#pragma unroll
    for (int m = 0; m < 16; m++) {
        float h = fmaxf(fmaf(q, cls[m], cls[16+m]), 0.f);
        o0 = fmaf(h, cls[32+2*m], o0);
        o1 = fmaf(h, cls[33+2*m], o1);
    }
    float2 res; res.x = o0; res.y = o1;
    ((float2*)out)[base + tid] = res;
}

// ---------------------------------------------------------------------------
extern "C" void kernel_launch(void* const* d_in, const int* in_sizes, int n_in,
                              void* d_out, int out_size) {
    const float* text = (const float*)d_in[0];
    const float* image= (const float*)d_in[1];
    const float* tW1  = (const float*)d_in[2];
    const float* tb1  = (const float*)d_in[3];
    const float* tW2  = (const float*)d_in[4];
    const float* tb2  = (const float*)d_in[5];
    const float* iW1  = (const float*)d_in[6];
    const float* ib1  = (const float*)d_in[7];
    const float* iW2  = (const float*)d_in[8];
    const float* ib2  = (const float*)d_in[9];
    const float* qw   = (const float*)d_in[10];
    const float* cW1  = (const float*)d_in[11];
    const float* cb1  = (const float*)d_in[12];
    const float* cW2  = (const float*)d_in[13];
    const float* cb2  = (const float*)d_in[14];
    float* out = (float*)d_out;

    const int B = in_sizes[0] / 16;
    const int grid = B / 128;
    const size_t smem = SMEM_FLOATS * sizeof(float);

    cudaFuncSetAttribute(qnn_kernel, cudaFuncAttributeMaxDynamicSharedMemorySize, (int)smem);

    build_M_kernel<<<1, 16>>>(qw);
    qnn_kernel<<<grid, 128, smem>>>(text, image, tW1, tb1, tW2, tb2,
                                    iW1, ib1, iW2, ib2,
                                    cW1, cb1, cW2, cb2, out);
}

// round 10
// speedup vs baseline: 1.1997x; 1.0443x over previous
#include <cuda_runtime.h>
#include <cstdint>

// ---------------------------------------------------------------------------
// QuantumNeuralNetwork: fused MLP + 4-qubit expval + classifier
//
// <Z0> = e^T M e with M = Re(U' Z0 U) precomputed by build_M_kernel.
//
// R9: packed fp32x2 math. GEMM accumulators packed in 64-bit pairs over the
// n-dimension and driven by PTX fma.rn.f32x2 (FFMA2) -> half the FMA-pipe
// instructions. b-operand pairs come free from ulonglong2 reinterpret of the
// float4 smem loads; a-operand broadcast-packed on the ALU pipe. Biases
// pre-folded into accumulator init. Fold + quantum M.e also packed.
// ---------------------------------------------------------------------------

#define XRS 49   // image tile row stride (floats), odd -> conflict-free LDS.32
#define XTS 17   // text  tile row stride

#define OFF_WI1A   0                        // [48][32] cols 0-31
#define OFF_WI1B   (48*32 + 4)              // [48][32] cols 32-63, +16B skew
#define OFF_XRI    (OFF_WI1B + 48*32 + 4)   // [128][XRS] image tile row-major
#define OFF_XRT    (OFF_XRI + 128*XRS)      // [128][XTS] text tile row-major
#define OFF_WT1    (OFF_XRT + 128*XTS)      // [16][32]
#define OFF_WI2    (OFF_WT1 + 512)          // [64][4] natural iW2
#define OFF_WT2    (OFF_WI2 + 256)          // [32][4] natural tW2
#define OFF_IB1    (OFF_WT2 + 128)          // [64]
#define OFF_TB1    (OFF_IB1 + 64)           // [32]
#define OFF_B2     (OFF_TB1 + 32)           // [4]
#define OFF_MS     (OFF_B2 + 4)             // [16][16]
#define OFF_CLS    (OFF_MS + 256)           // cW1[16] cb1[16] cW2[32] cb2[2]
#define SMEM_FLOATS (OFF_CLS + 68)

typedef unsigned long long ull;

#define FFMA2(d, a, b) \
    asm("fma.rn.f32x2 %0, %1, %2, %0;" : "+l"(d) : "l"(a), "l"(b))
#define MUL2(d, a, b) \
    asm("mul.rn.f32x2 %0, %1, %2;" : "=l"(d) : "l"(a), "l"(b))
#define ADD2(d, a, b) \
    asm("add.rn.f32x2 %0, %1, %2;" : "=l"(d) : "l"(a), "l"(b))
#define PACK2(out, lo, hi) \
    asm("mov.b64 %0, {%1, %2};" : "=l"(out) : "r"(__float_as_uint(lo)), "r"(__float_as_uint(hi)))
#define UNPACK2(lo, hi, v) do { unsigned _ulo, _uhi; \
    asm("mov.b64 {%0, %1}, %2;" : "=r"(_ulo), "=r"(_uhi) : "l"(v)); \
    lo = __uint_as_float(_ulo); hi = __uint_as_float(_uhi); } while (0)

__device__ __align__(16) float g_M[256];

// ---------------------------------------------------------------------------
// Prologue: build M[16][16] = Re(U^dagger Z0 U) from qweights [2][4][3].
// ---------------------------------------------------------------------------
__global__ void build_M_kernel(const float* __restrict__ qw) {
    __shared__ float Ure[16][16], Uim[16][16];
    const int k = threadIdx.x;  // column index 0..15
    float vr[16], vi[16];
#pragma unroll
    for (int n = 0; n < 16; n++) { vr[n] = (n == k) ? 1.f : 0.f; vi[n] = 0.f; }

    for (int l = 0; l < 2; l++) {
        for (int i = 0; i < 4; i++) {
            float phi = qw[(l*4 + i)*3 + 0];
            float th  = qw[(l*4 + i)*3 + 1];
            float om  = qw[(l*4 + i)*3 + 2];
            float ct = cosf(0.5f*th), st = sinf(0.5f*th);
            float sp, cp, sm, cm;
            sincosf(0.5f*(phi + om), &sp, &cp);
            sincosf(0.5f*(phi - om), &sm, &cm);
            float u00r =  cp*ct, u00i = -sp*ct;
            float u01r = -cm*st, u01i = -sm*st;
            float u10r =  cm*st, u10i = -sm*st;
            float u11r =  cp*ct, u11i =  sp*ct;
            int mask = 1 << (3 - i);
#pragma unroll
            for (int n = 0; n < 16; n++) {
                if (n & mask) continue;
                int n1 = n | mask;
                float r0 = vr[n],  i0 = vi[n];
                float r1 = vr[n1], i1 = vi[n1];
                vr[n]  = u00r*r0 - u00i*i0 + u01r*r1 - u01i*i1;
                vi[n]  = u00r*i0 + u00i*r0 + u01r*i1 + u01i*r1;
                vr[n1] = u10r*r0 - u10i*i0 + u11r*r1 - u11i*i1;
                vi[n1] = u10r*i0 + u10i*r0 + u11r*i1 + u11i*r1;
            }
        }
        for (int i = 0; i < 3; i++) {
            int m1 = 1 << (3 - i), m2 = 1 << (2 - i);
#pragma unroll
            for (int n = 0; n < 16; n++)
                if ((n & m1) && (n & m2)) { vr[n] = -vr[n]; vi[n] = -vi[n]; }
        }
    }
#pragma unroll
    for (int n = 0; n < 16; n++) { Ure[n][k] = vr[n]; Uim[n][k] = vi[n]; }
    __syncthreads();
#pragma unroll
    for (int j = 0; j < 16; j++) {
        float acc = 0.f;
#pragma unroll
        for (int b = 0; b < 16; b++) {
            float z = (b & 8) ? -1.f : 1.f;
            acc += z * (Ure[b][j]*Ure[b][k] + Uim[b][j]*Uim[b][k]);
        }
        g_M[j*16 + k] = acc;
    }
}

// ---------------------------------------------------------------------------
// Main fused kernel: 128 threads handle 128 samples per block.
// ---------------------------------------------------------------------------
__global__ __launch_bounds__(128) void qnn_kernel(
    const float* __restrict__ text, const float* __restrict__ image,
    const float* __restrict__ tW1,  const float* __restrict__ tb1,
    const float* __restrict__ tW2,  const float* __restrict__ tb2,
    const float* __restrict__ iW1,  const float* __restrict__ ib1,
    const float* __restrict__ iW2,  const float* __restrict__ ib2,
    const float* __restrict__ cW1,  const float* __restrict__ cb1,
    const float* __restrict__ cW2,  const float* __restrict__ cb2,
    float* __restrict__ out)
{
    extern __shared__ __align__(128) float smf[];
    float* wI1a = smf + OFF_WI1A;
    float* wI1b = smf + OFF_WI1B;
    float* xRi  = smf + OFF_XRI;
    float* xRt  = smf + OFF_XRT;
    float* wT1s = smf + OFF_WT1;
    float* wI2s = smf + OFF_WI2;   // [64][4] natural layout
    float* wT2s = smf + OFF_WT2;   // [32][4] natural layout
    float* ib1s = smf + OFF_IB1;
    float* tb1s = smf + OFF_TB1;
    float* b2s  = smf + OFF_B2;
    float* Ms   = smf + OFF_MS;
    float* cls  = smf + OFF_CLS;
    float* feats = xRi;            // aliased after GEMMs: [128][4]

    const int tid = threadIdx.x;
    const size_t base = (size_t)blockIdx.x * 128;

    // ---- stage inputs + weights into shared ----
    {
        const float4* ig = (const float4*)(image + base * 48);
#pragma unroll
        for (int it = 0; it < 12; it++) {
            int idx = it*128 + tid;
            float4 v = ig[idx];
            int s  = idx / 12;
            int kq = idx - s*12;
            float* p = &xRi[s*XRS + 4*kq];
            p[0] = v.x; p[1] = v.y; p[2] = v.z; p[3] = v.w;
        }
        const float4* tg = (const float4*)(text + base * 16);
#pragma unroll
        for (int it = 0; it < 4; it++) {
            int idx = it*128 + tid;
            float4 v = tg[idx];
            int s  = idx >> 2;
            int kq = idx & 3;
            float* p = &xRt[s*XTS + 4*kq];
            p[0] = v.x; p[1] = v.y; p[2] = v.z; p[3] = v.w;
        }
        // iW1 [48][64] -> split halves with 16B-skewed second half
#pragma unroll
        for (int it = 0; it < 6; it++) {
            int idx = it*128 + tid;            // float4 index 0..767
            float4 v = ((const float4*)iW1)[idx];
            int kk = idx >> 4;                 // row 0..47
            int nb = idx & 15;                 // block-of-4 within row
            float* dst = (nb < 8) ? &wI1a[kk*32 + nb*4]
                                  : &wI1b[kk*32 + (nb-8)*4];
            *(float4*)dst = v;
        }
        ((float4*)wT1s)[tid] = ((const float4*)tW1)[tid];
        if (tid < 64) {
            ((float4*)wI2s)[tid] = ((const float4*)iW2)[tid];  // natural [64][4]
            ib1s[tid] = ib1[tid];
            ((float4*)Ms)[tid] = ((const float4*)g_M)[tid];
        }
        if (tid < 32) {
            ((float4*)wT2s)[tid] = ((const float4*)tW2)[tid];  // natural [32][4]
            tb1s[tid] = tb1[tid];
        }
        if (tid < 16) {
            cls[tid] = cW1[tid]; cls[16+tid] = cb1[tid];
            cls[32+2*tid] = cW2[2*tid]; cls[33+2*tid] = cW2[2*tid+1];
        }
        if (tid < 4) b2s[tid] = ib2[tid] + tb2[tid];
        if (tid < 2) cls[64+tid] = cb2[tid];
    }
    __syncthreads();

    const int trow = tid >> 3;        // 0..15 : sample group
    const int tcol = tid & 7;         // 0..7  : neuron group
    const int m0 = trow * 8;

    // ---- image MLP1: 128x64, K=48, microtile 8x8, packed f32x2 over n ----
    const int n0 = tcol * 8;
    const float* wb = (tcol < 4) ? (wI1a + n0) : (wI1b + (n0 - 32));
    const float* xb = xRi + m0 * XRS;

    ull acc[8][4];
    {
        // init with layer-1 bias pairs (pre-folds the epilogue bias add)
        ulonglong2 bb0 = *(const ulonglong2*)&ib1s[n0];
        ulonglong2 bb1 = *(const ulonglong2*)&ib1s[n0 + 4];
#pragma unroll
        for (int i = 0; i < 8; i++) {
            acc[i][0] = bb0.x; acc[i][1] = bb0.y;
            acc[i][2] = bb1.x; acc[i][3] = bb1.y;
        }
    }

#pragma unroll 8
    for (int k = 0; k < 48; k++) {
        ulonglong2 b01 = *(const ulonglong2*)&wb[k*32];      // (b0,b1),(b2,b3)
        ulonglong2 b23 = *(const ulonglong2*)&wb[k*32 + 4];  // (b4,b5),(b6,b7)
#pragma unroll
        for (int i = 0; i < 8; i++) {
            float av = xb[i*XRS + k];
            ull aa; PACK2(aa, av, av);
            FFMA2(acc[i][0], aa, b01.x);
            FFMA2(acc[i][1], aa, b01.y);
            FFMA2(acc[i][2], aa, b23.x);
            FFMA2(acc[i][3], aa, b23.y);
        }
    }

    // ---- fold into imf partials: relu(h)·iW2, packed over the 4 outputs ----
    ull pv[8][2];
#pragma unroll
    for (int i = 0; i < 8; i++) { pv[i][0] = 0ull; pv[i][1] = 0ull; }

#pragma unroll
    for (int jj = 0; jj < 4; jj++) {     // j = 2jj, 2jj+1
        int nj0 = n0 + 2*jj;
        ulonglong2 wA = *(const ulonglong2*)&wI2s[nj0*4];       // (w0,w1),(w2,w3) of j0
        ulonglong2 wB = *(const ulonglong2*)&wI2s[(nj0+1)*4];   // of j1
#pragma unroll
        for (int i = 0; i < 8; i++) {
            float h0, h1;
            UNPACK2(h0, h1, acc[i][jj]);
            h0 = fmaxf(h0, 0.f); h1 = fmaxf(h1, 0.f);
            ull hh0, hh1; PACK2(hh0, h0, h0); PACK2(hh1, h1, h1);
            FFMA2(pv[i][0], hh0, wA.x);
            FFMA2(pv[i][1], hh0, wA.y);
            FFMA2(pv[i][0], hh1, wB.x);
            FFMA2(pv[i][1], hh1, wB.y);
        }
    }

    // ---- text MLP1: 128x32, K=16, microtile 8x4, packed ----
    const int t0 = tcol * 4;
    const float* xt = xRt + m0 * XTS;
    ull acc2[8][2];
    {
        ulonglong2 bb = *(const ulonglong2*)&tb1s[t0];
#pragma unroll
        for (int i = 0; i < 8; i++) { acc2[i][0] = bb.x; acc2[i][1] = bb.y; }
    }

#pragma unroll
    for (int k = 0; k < 16; k++) {
        ulonglong2 b01 = *(const ulonglong2*)&wT1s[k*32 + t0];
#pragma unroll
        for (int i = 0; i < 8; i++) {
            float av = xt[i*XTS + k];
            ull aa; PACK2(aa, av, av);
            FFMA2(acc2[i][0], aa, b01.x);
            FFMA2(acc2[i][1], aa, b01.y);
        }
    }
#pragma unroll
    for (int jj = 0; jj < 2; jj++) {     // j = 2jj, 2jj+1
        int nj0 = t0 + 2*jj;
        ulonglong2 wA = *(const ulonglong2*)&wT2s[nj0*4];
        ulonglong2 wB = *(const ulonglong2*)&wT2s[(nj0+1)*4];
#pragma unroll
        for (int i = 0; i < 8; i++) {
            float h0, h1;
            UNPACK2(h0, h1, acc2[i][jj]);
            h0 = fmaxf(h0, 0.f); h1 = fmaxf(h1, 0.f);
            ull hh0, hh1; PACK2(hh0, h0, h0); PACK2(hh1, h1, h1);
            FFMA2(pv[i][0], hh0, wA.x);
            FFMA2(pv[i][1], hh0, wA.y);
            FFMA2(pv[i][0], hh1, wB.x);
            FFMA2(pv[i][1], hh1, wB.y);
        }
    }

    // ---- reduce partials across the 8 neuron-group lanes ----
#pragma unroll
    for (int i = 0; i < 8; i++)
#pragma unroll
        for (int n = 0; n < 2; n++) {
            ull v = pv[i][n];
            ull t;
            t = __shfl_xor_sync(0xffffffffu, v, 4); ADD2(v, v, t);
            t = __shfl_xor_sync(0xffffffffu, v, 2); ADD2(v, v, t);
            t = __shfl_xor_sync(0xffffffffu, v, 1); ADD2(v, v, t);
            pv[i][n] = v;
        }

    __syncthreads();   // everyone done reading xRi/xRt before feats alias write
    if (tcol == 0) {
        ulonglong2 bb = *(const ulonglong2*)b2s;
        ull half2p; PACK2(half2p, 0.5f, 0.5f);
#pragma unroll
        for (int i = 0; i < 8; i++) {
            ull s0, s1;
            ADD2(s0, pv[i][0], bb.x);
            ADD2(s1, pv[i][1], bb.y);
            MUL2(s0, s0, half2p);
            MUL2(s1, s1, half2p);
            ulonglong2 fo; fo.x = s0; fo.y = s1;
            *(ulonglong2*)&feats[(m0 + i) * 4] = fo;
        }
    }
    __syncthreads();

    // ---- quantum expval + classifier: one sample per thread ----
    float4 f = *(const float4*)&feats[tid * 4];
    float c0, q0s, c1, q1s, c2, q2s, c3, q3s;
    __sincosf(0.5f*f.x, &q0s, &c0);
    __sincosf(0.5f*f.y, &q1s, &c1);
    __sincosf(0.5f*f.z, &q2s, &c2);
    __sincosf(0.5f*f.w, &q3s, &c3);

    float p01[4] = {c0*c1, c0*q1s, q0s*c1, q0s*q1s};
    float p23[4] = {c2*c3, c2*q3s, q2s*c3, q2s*q3s};

    // e pairs: e2[a*2+h] = (p01[a]*p23[2h], p01[a]*p23[2h+1])
    ull p23p0, p23p1;
    PACK2(p23p0, p23[0], p23[1]);
    PACK2(p23p1, p23[2], p23[3]);
    ull e2[8];
    float e[16];
#pragma unroll
    for (int a = 0; a < 4; a++) {
        ull pa; PACK2(pa, p01[a], p01[a]);
        MUL2(e2[a*2+0], pa, p23p0);
        MUL2(e2[a*2+1], pa, p23p1);
        UNPACK2(e[a*4+0], e[a*4+1], e2[a*2+0]);
        UNPACK2(e[a*4+2], e[a*4+3], e2[a*2+1]);
    }

    float q = 0.f;
#pragma unroll
    for (int j = 0; j < 16; j++) {
        const ulonglong2* Mr = (const ulonglong2*)&Ms[j*16];
        ulonglong2 m0v = Mr[0], m1v = Mr[1], m2v = Mr[2], m3v = Mr[3];
        ull t2 = 0ull;
        FFMA2(t2, m0v.x, e2[0]); FFMA2(t2, m0v.y, e2[1]);
        FFMA2(t2, m1v.x, e2[2]); FFMA2(t2, m1v.y, e2[3]);
        FFMA2(t2, m2v.x, e2[4]); FFMA2(t2, m2v.y, e2[5]);
        FFMA2(t2, m3v.x, e2[6]); FFMA2(t2, m3v.y, e2[7]);
        float tl, th; UNPACK2(tl, th, t2);
        q = fmaf(e[j], tl + th, q);
    }

    float o0 = cls[64], o1 = cls[65];
#pragma unroll
    for (int m = 0; m < 16; m++) {
        float h = fmaxf(fmaf(q, cls[m], cls[16+m]), 0.f);
        o0 = fmaf(h, cls[32+2*m], o0);
        o1 = fmaf(h, cls[33+2*m], o1);
    }
    float2 res; res.x = o0; res.y = o1;
    ((float2*)out)[base + tid] = res;
}

// ---------------------------------------------------------------------------
extern "C" void kernel_launch(void* const* d_in, const int* in_sizes, int n_in,
                              void* d_out, int out_size) {
    const float* text = (const float*)d_in[0];
    const float* image= (const float*)d_in[1];
    const float* tW1  = (const float*)d_in[2];
    const float* tb1  = (const float*)d_in[3];
    const float* tW2  = (const float*)d_in[4];
    const float* tb2  = (const float*)d_in[5];
    const float* iW1  = (const float*)d_in[6];
    const float* ib1  = (const float*)d_in[7];
    const float* iW2  = (const float*)d_in[8];
    const float* ib2  = (const float*)d_in[9];
    const float* qw   = (const float*)d_in[10];
    const float* cW1  = (const float*)d_in[11];
    const float* cb1  = (const float*)d_in[12];
    const float* cW2  = (const float*)d_in[13];
    const float* cb2  = (const float*)d_in[14];
    float* out = (float*)d_out;

    const int B = in_sizes[0] / 16;
    const int grid = B / 128;
    const size_t smem = SMEM_FLOATS * sizeof(float);

    cudaFuncSetAttribute(qnn_kernel, cudaFuncAttributeMaxDynamicSharedMemorySize, (int)smem);

    build_M_kernel<<<1, 16>>>(qw);
    qnn_kernel<<<grid, 128, smem>>>(text, image, tW1, tb1, tW2, tb2,
                                    iW1, ib1, iW2, ib2,
                                    cW1, cb1, cW2, cb2, out);
}